// round 1
// baseline (speedup 1.0000x reference)
#include <cuda_runtime.h>
#include <math.h>

#define NXD 1024
#define NHD 1024
#define BD  8
#define TD  2048

// Scratch (device globals: allocation-free rule)
__device__ float g_Q[BD * TD * NHD];          // 64 MiB
__device__ float g_K[BD * TD * NHD];          // 64 MiB
__device__ float g_V[BD * TD * NHD];          // 64 MiB
__device__ float g_S[(size_t)BD * TD * TD];   // 128 MiB
__device__ float g_A[BD * TD * NHD];          // 64 MiB

// ---------------------------------------------------------------------------
// GEMM NT: C[M,N] = alpha * A[M,K] * B[N,K]^T   (both row-major, K contiguous)
// Tiles: BM=128, BN=64, BK=16. 256 threads, each computes 8x4.
// Assumes M%128==0, N%64==0, K%16==0 (true for all shapes here).
// ---------------------------------------------------------------------------
__global__ __launch_bounds__(256) void gemm_nt(
    const float* __restrict__ Ag, const float* __restrict__ Bg,
    float* __restrict__ Cg, int M, int N, int K, float alpha,
    size_t sA, size_t sB, size_t sC)
{
    const int BM = 128, BN = 64, BK = 16;
    __shared__ float As[BK][BM + 4];
    __shared__ float Bs[BK][BN + 4];

    const float* Ab = Ag + blockIdx.z * sA + (size_t)blockIdx.y * BM * K;
    const float* Bb = Bg + blockIdx.z * sB + (size_t)blockIdx.x * BN * K;
    float*       Cb = Cg + blockIdx.z * sC + (size_t)blockIdx.y * BM * N
                         + (size_t)blockIdx.x * BN;

    const int tid = threadIdx.x;
    const int tx = tid & 15;      // 0..15 -> 4 cols each
    const int ty = tid >> 4;      // 0..15 -> 8 rows each

    float acc[8][4];
#pragma unroll
    for (int i = 0; i < 8; i++)
#pragma unroll
        for (int j = 0; j < 4; j++) acc[i][j] = 0.f;

    for (int k0 = 0; k0 < K; k0 += BK) {
        // Load A tile: 128x16 = 512 float4, 2 per thread
#pragma unroll
        for (int l = 0; l < 2; l++) {
            int idx = tid + l * 256;
            int row = idx >> 2;            // 0..127
            int kv  = (idx & 3) << 2;      // 0,4,8,12
            float4 v = *(const float4*)(Ab + (size_t)row * K + k0 + kv);
            As[kv + 0][row] = v.x; As[kv + 1][row] = v.y;
            As[kv + 2][row] = v.z; As[kv + 3][row] = v.w;
        }
        // Load B tile: 64x16 = 256 float4, 1 per thread
        {
            int row = tid >> 2;            // 0..63
            int kv  = (tid & 3) << 2;
            float4 v = *(const float4*)(Bb + (size_t)row * K + k0 + kv);
            Bs[kv + 0][row] = v.x; Bs[kv + 1][row] = v.y;
            Bs[kv + 2][row] = v.z; Bs[kv + 3][row] = v.w;
        }
        __syncthreads();

#pragma unroll
        for (int k = 0; k < BK; k++) {
            float4 a0 = *(const float4*)&As[k][ty * 8];
            float4 a1 = *(const float4*)&As[k][ty * 8 + 4];
            float4 b  = *(const float4*)&Bs[k][tx * 4];
            float ar[8] = {a0.x, a0.y, a0.z, a0.w, a1.x, a1.y, a1.z, a1.w};
            float br[4] = {b.x, b.y, b.z, b.w};
#pragma unroll
            for (int i = 0; i < 8; i++)
#pragma unroll
                for (int j = 0; j < 4; j++)
                    acc[i][j] = fmaf(ar[i], br[j], acc[i][j]);
        }
        __syncthreads();
    }

#pragma unroll
    for (int i = 0; i < 8; i++) {
        int row = ty * 8 + i;
        float4 o = make_float4(acc[i][0] * alpha, acc[i][1] * alpha,
                               acc[i][2] * alpha, acc[i][3] * alpha);
        *(float4*)(Cb + (size_t)row * N + tx * 4) = o;
    }
}

// ---------------------------------------------------------------------------
// GEMM NN: C[M,N] = A[M,K] * B[K,N]   (row-major; B has N contiguous)
// Same tiling as gemm_nt.
// ---------------------------------------------------------------------------
__global__ __launch_bounds__(256) void gemm_nn(
    const float* __restrict__ Ag, const float* __restrict__ Bg,
    float* __restrict__ Cg, int M, int N, int K,
    size_t sA, size_t sB, size_t sC)
{
    const int BM = 128, BN = 64, BK = 16;
    __shared__ float As[BK][BM + 4];
    __shared__ float Bs[BK][BN + 4];

    const float* Ab = Ag + blockIdx.z * sA + (size_t)blockIdx.y * BM * K;
    const float* Bb = Bg + blockIdx.z * sB + (size_t)blockIdx.x * BN;
    float*       Cb = Cg + blockIdx.z * sC + (size_t)blockIdx.y * BM * N
                         + (size_t)blockIdx.x * BN;

    const int tid = threadIdx.x;
    const int tx = tid & 15;
    const int ty = tid >> 4;

    float acc[8][4];
#pragma unroll
    for (int i = 0; i < 8; i++)
#pragma unroll
        for (int j = 0; j < 4; j++) acc[i][j] = 0.f;

    for (int k0 = 0; k0 < K; k0 += BK) {
        // Load A tile (same as NT)
#pragma unroll
        for (int l = 0; l < 2; l++) {
            int idx = tid + l * 256;
            int row = idx >> 2;
            int kv  = (idx & 3) << 2;
            float4 v = *(const float4*)(Ab + (size_t)row * K + k0 + kv);
            As[kv + 0][row] = v.x; As[kv + 1][row] = v.y;
            As[kv + 2][row] = v.z; As[kv + 3][row] = v.w;
        }
        // Load B tile: 16 k-rows x 64 n-cols, direct (coalesced along N)
        {
            int krow = tid >> 4;            // 0..15
            int col  = (tid & 15) << 2;     // 0..60
            float4 v = *(const float4*)(Bb + (size_t)(k0 + krow) * N + col);
            *(float4*)&Bs[krow][col] = v;
        }
        __syncthreads();

#pragma unroll
        for (int k = 0; k < BK; k++) {
            float4 a0 = *(const float4*)&As[k][ty * 8];
            float4 a1 = *(const float4*)&As[k][ty * 8 + 4];
            float4 b  = *(const float4*)&Bs[k][tx * 4];
            float ar[8] = {a0.x, a0.y, a0.z, a0.w, a1.x, a1.y, a1.z, a1.w};
            float br[4] = {b.x, b.y, b.z, b.w};
#pragma unroll
            for (int i = 0; i < 8; i++)
#pragma unroll
                for (int j = 0; j < 4; j++)
                    acc[i][j] = fmaf(ar[i], br[j], acc[i][j]);
        }
        __syncthreads();
    }

#pragma unroll
    for (int i = 0; i < 8; i++) {
        int row = ty * 8 + i;
        *(float4*)(Cb + (size_t)row * N + tx * 4) =
            make_float4(acc[i][0], acc[i][1], acc[i][2], acc[i][3]);
    }
}

// ---------------------------------------------------------------------------
// Row softmax over length T=2048. One block (256 threads) per row.
// ---------------------------------------------------------------------------
__global__ __launch_bounds__(256) void softmax_rows(float* __restrict__ S)
{
    float* row = S + (size_t)blockIdx.x * TD;
    __shared__ float red[256];
    const int tid = threadIdx.x;

    float v[8];
    float m = -INFINITY;
#pragma unroll
    for (int i = 0; i < 8; i++) {
        v[i] = row[tid + i * 256];
        m = fmaxf(m, v[i]);
    }
    red[tid] = m;
    __syncthreads();
    for (int s = 128; s > 0; s >>= 1) {
        if (tid < s) red[tid] = fmaxf(red[tid], red[tid + s]);
        __syncthreads();
    }
    m = red[0];
    __syncthreads();

    float sum = 0.f;
#pragma unroll
    for (int i = 0; i < 8; i++) {
        v[i] = __expf(v[i] - m);
        sum += v[i];
    }
    red[tid] = sum;
    __syncthreads();
    for (int s = 128; s > 0; s >>= 1) {
        if (tid < s) red[tid] += red[tid + s];
        __syncthreads();
    }
    float inv = 1.f / red[0];
#pragma unroll
    for (int i = 0; i < 8; i++)
        row[tid + i * 256] = v[i] * inv;
}

// ---------------------------------------------------------------------------
extern "C" void kernel_launch(void* const* d_in, const int* in_sizes, int n_in,
                              void* d_out, int out_size)
{
    const float* x   = (const float*)d_in[0];  // [8,2048,1024]
    const float* W_q = (const float*)d_in[1];  // [1024,1024]
    const float* W_k = (const float*)d_in[2];
    const float* W_v = (const float*)d_in[3];
    const float* W_o = (const float*)d_in[4];
    float* out = (float*)d_out;                // [8,2048,1024]

    float* Q; cudaGetSymbolAddress((void**)&Q, g_Q);
    float* K; cudaGetSymbolAddress((void**)&K, g_K);
    float* V; cudaGetSymbolAddress((void**)&V, g_V);
    float* S; cudaGetSymbolAddress((void**)&S, g_S);
    float* A; cudaGetSymbolAddress((void**)&A, g_A);

    const int M  = BD * TD;   // 16384
    const float scale = 1.0f / sqrtf((float)TD);

    // Q, K, V = x @ W^T   [16384,1024] x [1024,1024]^T
    {
        dim3 grid(NHD / 64, M / 128, 1);
        gemm_nt<<<grid, 256>>>(x, W_q, Q, M, NHD, NXD, 1.f, 0, 0, 0);
        gemm_nt<<<grid, 256>>>(x, W_k, K, M, NHD, NXD, 1.f, 0, 0, 0);
        gemm_nt<<<grid, 256>>>(x, W_v, V, M, NHD, NXD, 1.f, 0, 0, 0);
    }
    // S[b] = Q[b] @ K[b]^T * (1/sqrt(T))   [2048,2048] per batch
    {
        dim3 grid(TD / 64, TD / 128, BD);
        gemm_nt<<<grid, 256>>>(Q, K, S, TD, TD, NHD, scale,
                               (size_t)TD * NHD, (size_t)TD * NHD,
                               (size_t)TD * TD);
    }
    // softmax over last dim
    softmax_rows<<<BD * TD, 256>>>(S);

    // A[b] = P[b] @ V[b]   [2048,2048] x [2048,1024]
    {
        dim3 grid(NHD / 64, TD / 128, BD);
        gemm_nn<<<grid, 256>>>(S, V, A, TD, NHD, TD,
                               (size_t)TD * TD, (size_t)TD * NHD,
                               (size_t)TD * NHD);
    }
    // out = A @ W_o^T   [16384,1024] x [1024,1024]^T
    {
        dim3 grid(NHD / 64, M / 128, 1);
        gemm_nt<<<grid, 256>>>(A, W_o, out, M, NHD, NHD, 1.f, 0, 0, 0);
    }
}

// round 3
// speedup vs baseline: 1.9255x; 1.9255x over previous
#include <cuda_runtime.h>
#include <math.h>
#include <stdint.h>

#define NXD 1024
#define NHD 1024
#define BD  8
#define TD  2048

// ---------------- scratch (device globals; allocation-free rule) ------------
__device__ float g_Q [BD * TD * NHD];            // 64 MiB
__device__ float g_Kp[BD * TD * NHD];            // 64 MiB
__device__ float g_Vt[BD * TD * NHD];            // 64 MiB (V transposed: [b][NH][T])
__device__ float g_S [(size_t)BD * TD * TD];     // 128 MiB
__device__ float g_A [BD * TD * NHD];            // 64 MiB
__device__ float g_Xr[BD * TD * NXD];            // 64 MiB (x rounded to tf32)
__device__ float g_Wr[4u * NHD * NXD];           // 16 MiB (rounded weights)

// ---------------- helpers ----------------------------------------------
__device__ __forceinline__ uint32_t smem_u32(const void* p) {
    uint32_t a;
    asm("{ .reg .u64 t; cvta.to.shared.u64 t, %1; cvt.u32.u64 %0, t; }"
        : "=r"(a) : "l"(p));
    return a;
}
__device__ __forceinline__ float tf32r(float x) {
    uint32_t u;
    asm("cvt.rna.tf32.f32 %0, %1;" : "=r"(u) : "f"(x));
    return __uint_as_float(u);
}
__device__ __forceinline__ void cp_async16(uint32_t dst, const void* src) {
    asm volatile("cp.async.cg.shared.global [%0], [%1], 16;"
                 :: "r"(dst), "l"(src) : "memory");
}
__device__ __forceinline__ void mma_tf32(float c[4], const float a[4], const float b[2]) {
    asm volatile(
        "mma.sync.aligned.m16n8k8.row.col.f32.tf32.tf32.f32 "
        "{%0,%1,%2,%3}, {%4,%5,%6,%7}, {%8,%9}, {%0,%1,%2,%3};"
        : "+f"(c[0]), "+f"(c[1]), "+f"(c[2]), "+f"(c[3])
        : "r"(__float_as_uint(a[0])), "r"(__float_as_uint(a[1])),
          "r"(__float_as_uint(a[2])), "r"(__float_as_uint(a[3])),
          "r"(__float_as_uint(b[0])), "r"(__float_as_uint(b[1])));
}

// ---------------------------------------------------------------------------
// tf32 mma.sync GEMM NT: C[M,N] = alpha * A[M,K] * B[N,K]^T
// CTA 128x128, BK=32, 256 threads (8 warps, 2x4), warp tile 64x32.
// 3-stage cp.async pipeline. Requires M%128==0, N%128==0, K%32==0.
// ---------------------------------------------------------------------------
#define LROW 36                               // 32 + 4 pad (floats)
#define STG_FLOATS (2 * 128 * LROW)           // A tile + B tile per stage
#define N_STAGES 3
#define GT_SMEM (N_STAGES * STG_FLOATS * 4)   // 110592 B

__global__ __launch_bounds__(256, 1)
void gemm_mma(const float* __restrict__ Ag, const float* __restrict__ Bg,
              float* __restrict__ Cg, int M, int N, int K, float alpha,
              int do_round, size_t sA, size_t sB, size_t sC)
{
    extern __shared__ float sm[];
    const uint32_t sbase = smem_u32(sm);

    const int tid  = threadIdx.x;
    const int wid  = tid >> 5;
    const int lane = tid & 31;
    const int wm   = wid >> 2;        // 0..1  (64-row slab)
    const int wn   = wid & 3;         // 0..3  (32-col slab)
    const int g    = lane >> 2;       // groupID 0..7
    const int tig  = lane & 3;        // thread-in-group

    const float* Ab = Ag + blockIdx.z * sA + (size_t)blockIdx.y * 128 * K;
    const float* Bb = Bg + blockIdx.z * sB + (size_t)blockIdx.x * 128 * K;

    float acc[4][4][4];
#pragma unroll
    for (int i = 0; i < 4; i++)
#pragma unroll
        for (int j = 0; j < 4; j++)
#pragma unroll
            for (int r = 0; r < 4; r++) acc[i][j][r] = 0.f;

    const int nk = K >> 5;

    auto load_stage = [&](int js) {
        uint32_t stF = (uint32_t)((js % N_STAGES) * STG_FLOATS);
        const float* ga = Ab + js * 32;
        const float* gb = Bb + js * 32;
#pragma unroll
        for (int i = 0; i < 4; i++) {
            int c   = tid + i * 256;          // 0..1023
            int row = c >> 3;                 // 0..127
            int fc  = (c & 7) << 2;           // float col 0..28
            uint32_t d = sbase + 4u * (stF + row * LROW + fc);
            cp_async16(d, ga + (size_t)row * K + fc);
            cp_async16(d + 4u * 128 * LROW, gb + (size_t)row * K + fc);
        }
        asm volatile("cp.async.commit_group;" ::: "memory");
    };

    load_stage(0);
    if (nk > 1) load_stage(1);

    for (int ks = 0; ks < nk; ks++) {
        asm volatile("cp.async.wait_group 1;" ::: "memory");
        __syncthreads();
        if (ks + 2 < nk) load_stage(ks + 2);

        const float* sa = sm + (ks % N_STAGES) * STG_FLOATS;
        const float* sb = sa + 128 * LROW;

#pragma unroll
        for (int k8 = 0; k8 < 4; k8++) {
            const int kk = k8 * 8;
            float af[4][4], bf[4][2];
#pragma unroll
            for (int i = 0; i < 4; i++) {
                int m0 = wm * 64 + i * 16;
                af[i][0] = sa[(m0 + g)     * LROW + kk + tig];
                af[i][1] = sa[(m0 + 8 + g) * LROW + kk + tig];
                af[i][2] = sa[(m0 + g)     * LROW + kk + tig + 4];
                af[i][3] = sa[(m0 + 8 + g) * LROW + kk + tig + 4];
            }
#pragma unroll
            for (int j = 0; j < 4; j++) {
                int n0 = wn * 32 + j * 8;
                bf[j][0] = sb[(n0 + g) * LROW + kk + tig];
                bf[j][1] = sb[(n0 + g) * LROW + kk + tig + 4];
            }
#pragma unroll
            for (int i = 0; i < 4; i++)
#pragma unroll
                for (int j = 0; j < 4; j++)
                    mma_tf32(acc[i][j], af[i], bf[j]);
        }
        __syncthreads();
    }

    // Epilogue
#pragma unroll
    for (int i = 0; i < 4; i++) {
        size_t row0 = (size_t)blockIdx.y * 128 + wm * 64 + i * 16 + g;
        size_t col  = (size_t)blockIdx.x * 128 + wn * 32 + tig * 2;
        float* Cr0 = Cg + blockIdx.z * sC + row0 * N + col;
        float* Cr1 = Cr0 + 8 * (size_t)N;
#pragma unroll
        for (int j = 0; j < 4; j++) {
            float2 lo = make_float2(acc[i][j][0] * alpha, acc[i][j][1] * alpha);
            float2 hi = make_float2(acc[i][j][2] * alpha, acc[i][j][3] * alpha);
            if (do_round) {
                lo.x = tf32r(lo.x); lo.y = tf32r(lo.y);
                hi.x = tf32r(hi.x); hi.y = tf32r(hi.y);
            }
            *(float2*)(Cr0 + j * 8) = lo;
            *(float2*)(Cr1 + j * 8) = hi;
        }
    }
}

// ---------------------------------------------------------------------------
// Elementwise round-to-tf32 (RN): removes HW truncation bias at MMA ingestion.
// ---------------------------------------------------------------------------
__global__ __launch_bounds__(256) void round_tf32_kernel(
    const float* __restrict__ in, float* __restrict__ out, int n4)
{
    int i = blockIdx.x * blockDim.x + threadIdx.x;
    if (i < n4) {
        float4 v = ((const float4*)in)[i];
        v.x = tf32r(v.x); v.y = tf32r(v.y); v.z = tf32r(v.z); v.w = tf32r(v.w);
        ((float4*)out)[i] = v;
    }
}

// ---------------------------------------------------------------------------
// Row softmax over T=2048; output rounded to tf32 (feeds the PV MMA).
// ---------------------------------------------------------------------------
__global__ __launch_bounds__(256) void softmax_rows(float* __restrict__ S)
{
    float* row = S + (size_t)blockIdx.x * TD;
    __shared__ float red[256];
    const int tid = threadIdx.x;

    float v[8];
    float m = -INFINITY;
#pragma unroll
    for (int i = 0; i < 8; i++) {
        v[i] = row[tid + i * 256];
        m = fmaxf(m, v[i]);
    }
    red[tid] = m;
    __syncthreads();
    for (int s = 128; s > 0; s >>= 1) {
        if (tid < s) red[tid] = fmaxf(red[tid], red[tid + s]);
        __syncthreads();
    }
    m = red[0];
    __syncthreads();

    float sum = 0.f;
#pragma unroll
    for (int i = 0; i < 8; i++) {
        v[i] = __expf(v[i] - m);
        sum += v[i];
    }
    red[tid] = sum;
    __syncthreads();
    for (int s = 128; s > 0; s >>= 1) {
        if (tid < s) red[tid] += red[tid + s];
        __syncthreads();
    }
    float inv = 1.f / red[0];
#pragma unroll
    for (int i = 0; i < 8; i++)
        row[tid + i * 256] = tf32r(v[i] * inv);
}

// ---------------------------------------------------------------------------
extern "C" void kernel_launch(void* const* d_in, const int* in_sizes, int n_in,
                              void* d_out, int out_size)
{
    const float* x   = (const float*)d_in[0];
    const float* W_q = (const float*)d_in[1];
    const float* W_k = (const float*)d_in[2];
    const float* W_v = (const float*)d_in[3];
    const float* W_o = (const float*)d_in[4];
    float* out = (float*)d_out;

    float* Q;  cudaGetSymbolAddress((void**)&Q,  g_Q);
    float* Kp; cudaGetSymbolAddress((void**)&Kp, g_Kp);
    float* Vt; cudaGetSymbolAddress((void**)&Vt, g_Vt);
    float* S;  cudaGetSymbolAddress((void**)&S,  g_S);
    float* A;  cudaGetSymbolAddress((void**)&A,  g_A);
    float* Xr; cudaGetSymbolAddress((void**)&Xr, g_Xr);
    float* Wr; cudaGetSymbolAddress((void**)&Wr, g_Wr);

    cudaFuncSetAttribute(gemm_mma, cudaFuncAttributeMaxDynamicSharedMemorySize, GT_SMEM);

    const int M = BD * TD;                        // 16384
    const float scale = 1.0f / sqrtf((float)TD);
    const size_t WN = (size_t)NHD * NXD;

    // Pre-round operands to tf32 (RN)
    round_tf32_kernel<<<(M * NXD / 4 + 255) / 256, 256>>>(x, Xr, M * NXD / 4);
    round_tf32_kernel<<<(int)(WN / 4 + 255) / 256, 256>>>(W_q, Wr + 0 * WN, (int)(WN / 4));
    round_tf32_kernel<<<(int)(WN / 4 + 255) / 256, 256>>>(W_k, Wr + 1 * WN, (int)(WN / 4));
    round_tf32_kernel<<<(int)(WN / 4 + 255) / 256, 256>>>(W_v, Wr + 2 * WN, (int)(WN / 4));
    round_tf32_kernel<<<(int)(WN / 4 + 255) / 256, 256>>>(W_o, Wr + 3 * WN, (int)(WN / 4));

    // Q = Xr @ Wq^T ; K = Xr @ Wk^T      [16384,1024]
    {
        dim3 g(NHD / 128, M / 128, 1);
        gemm_mma<<<g, 256, GT_SMEM>>>(Xr, Wr + 0 * WN, Q,  M, NHD, NXD, 1.f, 1, 0, 0, 0);
        gemm_mma<<<g, 256, GT_SMEM>>>(Xr, Wr + 1 * WN, Kp, M, NHD, NXD, 1.f, 1, 0, 0, 0);
    }
    // Vt[b] = Wv @ x_b^T                 [1024,2048] per batch
    {
        dim3 g(TD / 128, NHD / 128, BD);
        gemm_mma<<<g, 256, GT_SMEM>>>(Wr + 2 * WN, Xr, Vt, NHD, TD, NXD, 1.f, 1,
                                      0, (size_t)TD * NXD, (size_t)NHD * TD);
    }
    // S[b] = (Q_b @ K_b^T) / sqrt(T)     [2048,2048] per batch
    {
        dim3 g(TD / 128, TD / 128, BD);
        gemm_mma<<<g, 256, GT_SMEM>>>(Q, Kp, S, TD, TD, NHD, scale, 0,
                                      (size_t)TD * NHD, (size_t)TD * NHD,
                                      (size_t)TD * TD);
    }
    softmax_rows<<<BD * TD, 256>>>(S);

    // A[b] = P_b @ Vt_b^T                [2048,1024] per batch
    {
        dim3 g(NHD / 128, TD / 128, BD);
        gemm_mma<<<g, 256, GT_SMEM>>>(S, Vt, A, TD, NHD, TD, 1.f, 1,
                                      (size_t)TD * TD, (size_t)NHD * TD,
                                      (size_t)TD * NHD);
    }
    // out = A @ Wo^T                     [16384,1024]
    {
        dim3 g(NHD / 128, M / 128, 1);
        gemm_mma<<<g, 256, GT_SMEM>>>(A, Wr + 3 * WN, out, M, NHD, NHD, 1.f, 0, 0, 0, 0);
    }
}

// round 4
// speedup vs baseline: 1.9804x; 1.0285x over previous
#include <cuda_runtime.h>
#include <math.h>
#include <stdint.h>

#define NXD 1024
#define NHD 1024
#define BD  8
#define TD  2048

// ---------------- scratch (device globals; allocation-free rule) ------------
__device__ float g_Q [BD * TD * NHD];            // 64 MiB
__device__ float g_Kp[BD * TD * NHD];            // 64 MiB
__device__ float g_Vt[BD * TD * NHD];            // 64 MiB (V transposed: [b][NH][T])
__device__ float g_S [(size_t)BD * TD * TD];     // 128 MiB
__device__ float g_A [BD * TD * NHD];            // 64 MiB
__device__ float g_Xr[BD * TD * NXD];            // 64 MiB (x rounded to tf32)
__device__ float g_Wr[4u * NHD * NXD];           // 16 MiB (rounded weights)

// ---------------- helpers ----------------------------------------------
__device__ __forceinline__ uint32_t smem_u32(const void* p) {
    uint32_t a;
    asm("{ .reg .u64 t; cvta.to.shared.u64 t, %1; cvt.u32.u64 %0, t; }"
        : "=r"(a) : "l"(p));
    return a;
}
__device__ __forceinline__ float tf32r(float x) {
    uint32_t u;
    asm("cvt.rna.tf32.f32 %0, %1;" : "=r"(u) : "f"(x));
    return __uint_as_float(u);
}
__device__ __forceinline__ void cp_async16(uint32_t dst, const void* src) {
    asm volatile("cp.async.cg.shared.global [%0], [%1], 16;"
                 :: "r"(dst), "l"(src) : "memory");
}
__device__ __forceinline__ void mma_tf32(float c[4], const float a[4], const float b[2]) {
    asm volatile(
        "mma.sync.aligned.m16n8k8.row.col.f32.tf32.tf32.f32 "
        "{%0,%1,%2,%3}, {%4,%5,%6,%7}, {%8,%9}, {%0,%1,%2,%3};"
        : "+f"(c[0]), "+f"(c[1]), "+f"(c[2]), "+f"(c[3])
        : "r"(__float_as_uint(a[0])), "r"(__float_as_uint(a[1])),
          "r"(__float_as_uint(a[2])), "r"(__float_as_uint(a[3])),
          "r"(__float_as_uint(b[0])), "r"(__float_as_uint(b[1])));
}

// ---------------------------------------------------------------------------
// tf32 mma.sync GEMM NT: C[M,N] = alpha * A[M,K] * B[N,K]^T
// CTA 128x128, BK=32, 256 threads (8 warps, 2x4), warp tile 64x32.
// 4-stage cp.async pipeline (wait_group 2) + register-level fragment
// double buffering. Requires M%128==0, N%128==0, K%32==0.
// ---------------------------------------------------------------------------
#define LROW 36                               // 32 + 4 pad (floats)
#define STG_FLOATS (2 * 128 * LROW)           // A tile + B tile per stage
#define N_STAGES 4
#define GT_SMEM (N_STAGES * STG_FLOATS * 4)   // 147456 B

__global__ __launch_bounds__(256, 1)
void gemm_mma(const float* __restrict__ Ag, const float* __restrict__ Bg,
              float* __restrict__ Cg, int M, int N, int K, float alpha,
              int do_round, size_t sA, size_t sB, size_t sC)
{
    extern __shared__ float sm[];
    const uint32_t sbase = smem_u32(sm);

    const int tid  = threadIdx.x;
    const int wid  = tid >> 5;
    const int lane = tid & 31;
    const int wm   = wid >> 2;        // 0..1  (64-row slab)
    const int wn   = wid & 3;         // 0..3  (32-col slab)
    const int g    = lane >> 2;       // groupID 0..7
    const int tig  = lane & 3;        // thread-in-group

    const float* Ab = Ag + blockIdx.z * sA + (size_t)blockIdx.y * 128 * K;
    const float* Bb = Bg + blockIdx.z * sB + (size_t)blockIdx.x * 128 * K;

    float acc[4][4][4];
#pragma unroll
    for (int i = 0; i < 4; i++)
#pragma unroll
        for (int j = 0; j < 4; j++)
#pragma unroll
            for (int r = 0; r < 4; r++) acc[i][j][r] = 0.f;

    const int nk = K >> 5;

    auto load_stage = [&](int js) {
        uint32_t stF = (uint32_t)((js % N_STAGES) * STG_FLOATS);
        const float* ga = Ab + js * 32;
        const float* gb = Bb + js * 32;
#pragma unroll
        for (int i = 0; i < 4; i++) {
            int c   = tid + i * 256;          // 0..1023
            int row = c >> 3;                 // 0..127
            int fc  = (c & 7) << 2;           // float col 0..28
            uint32_t d = sbase + 4u * (stF + row * LROW + fc);
            cp_async16(d, ga + (size_t)row * K + fc);
            cp_async16(d + 4u * 128 * LROW, gb + (size_t)row * K + fc);
        }
        asm volatile("cp.async.commit_group;" ::: "memory");
    };

    load_stage(0);
    if (nk > 1) load_stage(1);
    if (nk > 2) load_stage(2);

    // fragment double buffers
    float af[2][4][4], bf[2][4][2];

    for (int ks = 0; ks < nk; ks++) {
        asm volatile("cp.async.wait_group 2;" ::: "memory");
        __syncthreads();

        const float* sa = sm + (ks % N_STAGES) * STG_FLOATS;
        const float* sb = sa + 128 * LROW;

        auto ldfrag = [&](int k8, int buf) {
            const int kk = k8 * 8;
#pragma unroll
            for (int i = 0; i < 4; i++) {
                int m0 = wm * 64 + i * 16;
                af[buf][i][0] = sa[(m0 + g)     * LROW + kk + tig];
                af[buf][i][1] = sa[(m0 + 8 + g) * LROW + kk + tig];
                af[buf][i][2] = sa[(m0 + g)     * LROW + kk + tig + 4];
                af[buf][i][3] = sa[(m0 + 8 + g) * LROW + kk + tig + 4];
            }
#pragma unroll
            for (int j = 0; j < 4; j++) {
                int n0 = wn * 32 + j * 8;
                bf[buf][j][0] = sb[(n0 + g) * LROW + kk + tig];
                bf[buf][j][1] = sb[(n0 + g) * LROW + kk + tig + 4];
            }
        };

        ldfrag(0, 0);
        if (ks + 3 < nk) load_stage(ks + 3);   // stage (ks-1)%4: safe after sync

#pragma unroll
        for (int k8 = 0; k8 < 4; k8++) {
            const int cur = k8 & 1;
            if (k8 < 3) ldfrag(k8 + 1, cur ^ 1);
#pragma unroll
            for (int i = 0; i < 4; i++)
#pragma unroll
                for (int j = 0; j < 4; j++)
                    mma_tf32(acc[i][j], af[cur][i], bf[cur][j]);
        }
    }

    // Epilogue
#pragma unroll
    for (int i = 0; i < 4; i++) {
        size_t row0 = (size_t)blockIdx.y * 128 + wm * 64 + i * 16 + g;
        size_t col  = (size_t)blockIdx.x * 128 + wn * 32 + tig * 2;
        float* Cr0 = Cg + blockIdx.z * sC + row0 * N + col;
        float* Cr1 = Cr0 + 8 * (size_t)N;
#pragma unroll
        for (int j = 0; j < 4; j++) {
            float2 lo = make_float2(acc[i][j][0] * alpha, acc[i][j][1] * alpha);
            float2 hi = make_float2(acc[i][j][2] * alpha, acc[i][j][3] * alpha);
            if (do_round) {
                lo.x = tf32r(lo.x); lo.y = tf32r(lo.y);
                hi.x = tf32r(hi.x); hi.y = tf32r(hi.y);
            }
            *(float2*)(Cr0 + j * 8) = lo;
            *(float2*)(Cr1 + j * 8) = hi;
        }
    }
}

// ---------------------------------------------------------------------------
// Elementwise round-to-tf32 (RN): removes HW truncation bias at MMA ingestion.
// ---------------------------------------------------------------------------
__global__ __launch_bounds__(256) void round_tf32_kernel(
    const float* __restrict__ in, float* __restrict__ out, int n4)
{
    int i = blockIdx.x * blockDim.x + threadIdx.x;
    if (i < n4) {
        float4 v = ((const float4*)in)[i];
        v.x = tf32r(v.x); v.y = tf32r(v.y); v.z = tf32r(v.z); v.w = tf32r(v.w);
        ((float4*)out)[i] = v;
    }
}

// ---------------------------------------------------------------------------
// Row softmax over T=2048; output rounded to tf32 (feeds the PV MMA).
// ---------------------------------------------------------------------------
__global__ __launch_bounds__(256) void softmax_rows(float* __restrict__ S)
{
    float* row = S + (size_t)blockIdx.x * TD;
    __shared__ float red[256];
    const int tid = threadIdx.x;

    float v[8];
    float m = -INFINITY;
#pragma unroll
    for (int i = 0; i < 8; i++) {
        v[i] = row[tid + i * 256];
        m = fmaxf(m, v[i]);
    }
    red[tid] = m;
    __syncthreads();
    for (int s = 128; s > 0; s >>= 1) {
        if (tid < s) red[tid] = fmaxf(red[tid], red[tid + s]);
        __syncthreads();
    }
    m = red[0];
    __syncthreads();

    float sum = 0.f;
#pragma unroll
    for (int i = 0; i < 8; i++) {
        v[i] = __expf(v[i] - m);
        sum += v[i];
    }
    red[tid] = sum;
    __syncthreads();
    for (int s = 128; s > 0; s >>= 1) {
        if (tid < s) red[tid] += red[tid + s];
        __syncthreads();
    }
    float inv = 1.f / red[0];
#pragma unroll
    for (int i = 0; i < 8; i++)
        row[tid + i * 256] = tf32r(v[i] * inv);
}

// ---------------------------------------------------------------------------
extern "C" void kernel_launch(void* const* d_in, const int* in_sizes, int n_in,
                              void* d_out, int out_size)
{
    const float* x   = (const float*)d_in[0];
    const float* W_q = (const float*)d_in[1];
    const float* W_k = (const float*)d_in[2];
    const float* W_v = (const float*)d_in[3];
    const float* W_o = (const float*)d_in[4];
    float* out = (float*)d_out;

    float* Q;  cudaGetSymbolAddress((void**)&Q,  g_Q);
    float* Kp; cudaGetSymbolAddress((void**)&Kp, g_Kp);
    float* Vt; cudaGetSymbolAddress((void**)&Vt, g_Vt);
    float* S;  cudaGetSymbolAddress((void**)&S,  g_S);
    float* A;  cudaGetSymbolAddress((void**)&A,  g_A);
    float* Xr; cudaGetSymbolAddress((void**)&Xr, g_Xr);
    float* Wr; cudaGetSymbolAddress((void**)&Wr, g_Wr);

    cudaFuncSetAttribute(gemm_mma, cudaFuncAttributeMaxDynamicSharedMemorySize, GT_SMEM);

    const int M = BD * TD;                        // 16384
    const float scale = 1.0f / sqrtf((float)TD);
    const size_t WN = (size_t)NHD * NXD;

    // Pre-round operands to tf32 (RN)
    round_tf32_kernel<<<(M * NXD / 4 + 255) / 256, 256>>>(x, Xr, M * NXD / 4);
    round_tf32_kernel<<<(int)(WN / 4 + 255) / 256, 256>>>(W_q, Wr + 0 * WN, (int)(WN / 4));
    round_tf32_kernel<<<(int)(WN / 4 + 255) / 256, 256>>>(W_k, Wr + 1 * WN, (int)(WN / 4));
    round_tf32_kernel<<<(int)(WN / 4 + 255) / 256, 256>>>(W_v, Wr + 2 * WN, (int)(WN / 4));
    round_tf32_kernel<<<(int)(WN / 4 + 255) / 256, 256>>>(W_o, Wr + 3 * WN, (int)(WN / 4));

    // Q = Xr @ Wq^T ; K = Xr @ Wk^T      [16384,1024]
    {
        dim3 g(NHD / 128, M / 128, 1);
        gemm_mma<<<g, 256, GT_SMEM>>>(Xr, Wr + 0 * WN, Q,  M, NHD, NXD, 1.f, 1, 0, 0, 0);
        gemm_mma<<<g, 256, GT_SMEM>>>(Xr, Wr + 1 * WN, Kp, M, NHD, NXD, 1.f, 1, 0, 0, 0);
    }
    // Vt[b] = Wv @ x_b^T                 [1024,2048] per batch
    {
        dim3 g(TD / 128, NHD / 128, BD);
        gemm_mma<<<g, 256, GT_SMEM>>>(Wr + 2 * WN, Xr, Vt, NHD, TD, NXD, 1.f, 1,
                                      0, (size_t)TD * NXD, (size_t)NHD * TD);
    }
    // S[b] = (Q_b @ K_b^T) / sqrt(T)     [2048,2048] per batch
    {
        dim3 g(TD / 128, TD / 128, BD);
        gemm_mma<<<g, 256, GT_SMEM>>>(Q, Kp, S, TD, TD, NHD, scale, 0,
                                      (size_t)TD * NHD, (size_t)TD * NHD,
                                      (size_t)TD * TD);
    }
    softmax_rows<<<BD * TD, 256>>>(S);

    // A[b] = P_b @ Vt_b^T                [2048,1024] per batch
    {
        dim3 g(NHD / 128, TD / 128, BD);
        gemm_mma<<<g, 256, GT_SMEM>>>(S, Vt, A, TD, NHD, TD, 1.f, 1,
                                      (size_t)TD * TD, (size_t)NHD * TD,
                                      (size_t)TD * NHD);
    }
    // out = A @ Wo^T                     [16384,1024]
    {
        dim3 g(NHD / 128, M / 128, 1);
        gemm_mma<<<g, 256, GT_SMEM>>>(A, Wr + 3 * WN, out, M, NHD, NHD, 1.f, 0, 0, 0, 0);
    }
}

// round 5
// speedup vs baseline: 5.5531x; 2.8040x over previous
#include <cuda_runtime.h>
#include <cuda_fp16.h>
#include <math.h>
#include <stdint.h>

#define NXD 1024
#define NHD 1024
#define BD  8
#define TD  2048

// ---------------- scratch (device globals; allocation-free rule) ------------
__device__ __half g_Xh[BD * TD * NXD];             // 32 MiB
__device__ __half g_Wh[4u * NHD * NXD];            // 8 MiB
__device__ __half g_Qh[BD * TD * NHD];             // 32 MiB
__device__ __half g_Kh[BD * TD * NHD];             // 32 MiB
__device__ __half g_Vth[BD * TD * NHD];            // 32 MiB (V transposed)
__device__ float  g_S [(size_t)BD * TD * TD];      // 128 MiB (f32 scores)
__device__ __half g_Ph[(size_t)BD * TD * TD];      // 64 MiB (half probs)
__device__ __half g_Ah[BD * TD * NHD];             // 32 MiB

// ---------------- helpers ----------------------------------------------
__device__ __forceinline__ uint32_t smem_u32(const void* p) {
    uint32_t a;
    asm("{ .reg .u64 t; cvta.to.shared.u64 t, %1; cvt.u32.u64 %0, t; }"
        : "=r"(a) : "l"(p));
    return a;
}
__device__ __forceinline__ void cp_async16(uint32_t dst, const void* src) {
    asm volatile("cp.async.cg.shared.global [%0], [%1], 16;"
                 :: "r"(dst), "l"(src) : "memory");
}
__device__ __forceinline__ void mma_f16(float c[4], const uint32_t a[4], const uint32_t b[2]) {
    asm volatile(
        "mma.sync.aligned.m16n8k16.row.col.f32.f16.f16.f32 "
        "{%0,%1,%2,%3}, {%4,%5,%6,%7}, {%8,%9}, {%0,%1,%2,%3};"
        : "+f"(c[0]), "+f"(c[1]), "+f"(c[2]), "+f"(c[3])
        : "r"(a[0]), "r"(a[1]), "r"(a[2]), "r"(a[3]),
          "r"(b[0]), "r"(b[1]));
}

// ---------------------------------------------------------------------------
// fp16 mma.sync GEMM NT: C[M,N] = alpha * A[M,K] * B[N,K]^T  (A,B half)
// CTA 128x128, BK=64 halves, 256 threads (8 warps 2x4), warp tile 64x32.
// 4-stage cp.async pipeline + fragment double buffering.
// out_half: 1 -> write __half C, 0 -> write float C.
// Requires M%128==0, N%128==0, K%64==0.
// ---------------------------------------------------------------------------
#define LROWH 72                               // 64 + 8 pad (halves); 144B/row
#define STG_HALVES (2 * 128 * LROWH)           // A + B tile per stage
#define N_STAGES 4
#define GT_SMEM (N_STAGES * STG_HALVES * 2)    // 147456 B

__global__ __launch_bounds__(256, 1)
void gemm_h(const __half* __restrict__ Ag, const __half* __restrict__ Bg,
            void* __restrict__ Cg, int M, int N, int K, float alpha,
            int out_half, size_t sA, size_t sB, size_t sC)
{
    extern __shared__ __half sm[];
    const uint32_t sbase = smem_u32(sm);

    const int tid  = threadIdx.x;
    const int wid  = tid >> 5;
    const int lane = tid & 31;
    const int wm   = wid >> 2;        // 0..1
    const int wn   = wid & 3;         // 0..3
    const int g    = lane >> 2;       // 0..7
    const int tig  = lane & 3;        // 0..3

    const __half* Ab = Ag + blockIdx.z * sA + (size_t)blockIdx.y * 128 * K;
    const __half* Bb = Bg + blockIdx.z * sB + (size_t)blockIdx.x * 128 * K;

    float acc[4][4][4];
#pragma unroll
    for (int i = 0; i < 4; i++)
#pragma unroll
        for (int j = 0; j < 4; j++)
#pragma unroll
            for (int r = 0; r < 4; r++) acc[i][j][r] = 0.f;

    const int nk = K >> 6;            // 64-half K steps

    auto load_stage = [&](int js) {
        uint32_t stH = (uint32_t)((js % N_STAGES) * STG_HALVES);
        const __half* ga = Ab + js * 64;
        const __half* gb = Bb + js * 64;
#pragma unroll
        for (int i = 0; i < 4; i++) {
            int c   = tid + i * 256;          // 0..1023 chunks of 16B
            int row = c >> 3;                 // 0..127
            int fh  = (c & 7) << 3;           // half col 0..56
            uint32_t d = sbase + 2u * (stH + row * LROWH + fh);
            cp_async16(d, ga + (size_t)row * K + fh);
            cp_async16(d + 2u * 128 * LROWH, gb + (size_t)row * K + fh);
        }
        asm volatile("cp.async.commit_group;" ::: "memory");
    };

    load_stage(0);
    if (nk > 1) load_stage(1);
    if (nk > 2) load_stage(2);

    uint32_t af[2][4][4], bf[2][4][2];

    for (int ks = 0; ks < nk; ks++) {
        asm volatile("cp.async.wait_group 2;" ::: "memory");
        __syncthreads();

        const __half* sa = sm + (ks % N_STAGES) * STG_HALVES;
        const __half* sb = sa + 128 * LROWH;

        auto ldfrag = [&](int k16, int buf) {
            const int kk = k16 * 16;
#pragma unroll
            for (int i = 0; i < 4; i++) {
                int m0 = wm * 64 + i * 16;
                af[buf][i][0] = *(const uint32_t*)&sa[(m0 + g)     * LROWH + kk + 2 * tig];
                af[buf][i][1] = *(const uint32_t*)&sa[(m0 + 8 + g) * LROWH + kk + 2 * tig];
                af[buf][i][2] = *(const uint32_t*)&sa[(m0 + g)     * LROWH + kk + 2 * tig + 8];
                af[buf][i][3] = *(const uint32_t*)&sa[(m0 + 8 + g) * LROWH + kk + 2 * tig + 8];
            }
#pragma unroll
            for (int j = 0; j < 4; j++) {
                int n0 = wn * 32 + j * 8;
                bf[buf][j][0] = *(const uint32_t*)&sb[(n0 + g) * LROWH + kk + 2 * tig];
                bf[buf][j][1] = *(const uint32_t*)&sb[(n0 + g) * LROWH + kk + 2 * tig + 8];
            }
        };

        ldfrag(0, 0);
        if (ks + 3 < nk) load_stage(ks + 3);

#pragma unroll
        for (int k16 = 0; k16 < 4; k16++) {
            const int cur = k16 & 1;
            if (k16 < 3) ldfrag(k16 + 1, cur ^ 1);
#pragma unroll
            for (int i = 0; i < 4; i++)
#pragma unroll
                for (int j = 0; j < 4; j++)
                    mma_f16(acc[i][j], af[cur][i], bf[cur][j]);
        }
    }

    // Epilogue
#pragma unroll
    for (int i = 0; i < 4; i++) {
        size_t row0 = (size_t)blockIdx.y * 128 + wm * 64 + i * 16 + g;
        size_t col  = (size_t)blockIdx.x * 128 + wn * 32 + tig * 2;
        if (out_half) {
            __half* C0 = (__half*)Cg + blockIdx.z * sC + row0 * N + col;
            __half* C1 = C0 + 8 * (size_t)N;
#pragma unroll
            for (int j = 0; j < 4; j++) {
                *(__half2*)(C0 + j * 8) = __float22half2_rn(
                    make_float2(acc[i][j][0] * alpha, acc[i][j][1] * alpha));
                *(__half2*)(C1 + j * 8) = __float22half2_rn(
                    make_float2(acc[i][j][2] * alpha, acc[i][j][3] * alpha));
            }
        } else {
            float* C0 = (float*)Cg + blockIdx.z * sC + row0 * N + col;
            float* C1 = C0 + 8 * (size_t)N;
#pragma unroll
            for (int j = 0; j < 4; j++) {
                *(float2*)(C0 + j * 8) =
                    make_float2(acc[i][j][0] * alpha, acc[i][j][1] * alpha);
                *(float2*)(C1 + j * 8) =
                    make_float2(acc[i][j][2] * alpha, acc[i][j][3] * alpha);
            }
        }
    }
}

// ---------------------------------------------------------------------------
// f32 -> f16 conversion (RN)
// ---------------------------------------------------------------------------
__global__ __launch_bounds__(256) void cvt_h_kernel(
    const float* __restrict__ in, __half* __restrict__ out, int n4)
{
    int i = blockIdx.x * blockDim.x + threadIdx.x;
    if (i < n4) {
        float4 v = ((const float4*)in)[i];
        __half2 lo = __float22half2_rn(make_float2(v.x, v.y));
        __half2 hi = __float22half2_rn(make_float2(v.z, v.w));
        *(uint2*)(out + 4 * (size_t)i) =
            make_uint2(*(uint32_t*)&lo, *(uint32_t*)&hi);
    }
}

// ---------------------------------------------------------------------------
// Row softmax over T=2048 on f32 scores; writes half probabilities.
// ---------------------------------------------------------------------------
__global__ __launch_bounds__(256) void softmax_rows(
    const float* __restrict__ S, __half* __restrict__ P)
{
    const float* row = S + (size_t)blockIdx.x * TD;
    __half* prow = P + (size_t)blockIdx.x * TD;
    __shared__ float red[256];
    const int tid = threadIdx.x;

    float v[8];
    float m = -INFINITY;
#pragma unroll
    for (int i = 0; i < 8; i++) {
        v[i] = row[tid * 8 + i];        // contiguous float4x2 per thread
        m = fmaxf(m, v[i]);
    }
    red[tid] = m;
    __syncthreads();
    for (int s = 128; s > 0; s >>= 1) {
        if (tid < s) red[tid] = fmaxf(red[tid], red[tid + s]);
        __syncthreads();
    }
    m = red[0];
    __syncthreads();

    float sum = 0.f;
#pragma unroll
    for (int i = 0; i < 8; i++) {
        v[i] = __expf(v[i] - m);
        sum += v[i];
    }
    red[tid] = sum;
    __syncthreads();
    for (int s = 128; s > 0; s >>= 1) {
        if (tid < s) red[tid] += red[tid + s];
        __syncthreads();
    }
    float inv = 1.f / red[0];
#pragma unroll
    for (int i = 0; i < 8; i += 2) {
        __half2 h = __float22half2_rn(make_float2(v[i] * inv, v[i + 1] * inv));
        *(__half2*)(prow + tid * 8 + i) = h;
    }
}

// ---------------------------------------------------------------------------
extern "C" void kernel_launch(void* const* d_in, const int* in_sizes, int n_in,
                              void* d_out, int out_size)
{
    const float* x   = (const float*)d_in[0];
    const float* W_q = (const float*)d_in[1];
    const float* W_k = (const float*)d_in[2];
    const float* W_v = (const float*)d_in[3];
    const float* W_o = (const float*)d_in[4];
    float* out = (float*)d_out;

    __half* Xh;  cudaGetSymbolAddress((void**)&Xh,  g_Xh);
    __half* Wh;  cudaGetSymbolAddress((void**)&Wh,  g_Wh);
    __half* Qh;  cudaGetSymbolAddress((void**)&Qh,  g_Qh);
    __half* Kh;  cudaGetSymbolAddress((void**)&Kh,  g_Kh);
    __half* Vth; cudaGetSymbolAddress((void**)&Vth, g_Vth);
    float*  S;   cudaGetSymbolAddress((void**)&S,   g_S);
    __half* Ph;  cudaGetSymbolAddress((void**)&Ph,  g_Ph);
    __half* Ah;  cudaGetSymbolAddress((void**)&Ah,  g_Ah);

    cudaFuncSetAttribute(gemm_h, cudaFuncAttributeMaxDynamicSharedMemorySize, GT_SMEM);

    const int M = BD * TD;                        // 16384
    const float scale = 1.0f / sqrtf((float)TD);
    const size_t WN = (size_t)NHD * NXD;

    // Convert operands to fp16 (RN)
    cvt_h_kernel<<<(M * NXD / 4 + 255) / 256, 256>>>(x, Xh, M * NXD / 4);
    cvt_h_kernel<<<(int)(WN / 4 + 255) / 256, 256>>>(W_q, Wh + 0 * WN, (int)(WN / 4));
    cvt_h_kernel<<<(int)(WN / 4 + 255) / 256, 256>>>(W_k, Wh + 1 * WN, (int)(WN / 4));
    cvt_h_kernel<<<(int)(WN / 4 + 255) / 256, 256>>>(W_v, Wh + 2 * WN, (int)(WN / 4));
    cvt_h_kernel<<<(int)(WN / 4 + 255) / 256, 256>>>(W_o, Wh + 3 * WN, (int)(WN / 4));

    // Qh = Xh @ Wq^T ; Kh = Xh @ Wk^T   [16384,1024] (half out)
    {
        dim3 g(NHD / 128, M / 128, 1);
        gemm_h<<<g, 256, GT_SMEM>>>(Xh, Wh + 0 * WN, Qh, M, NHD, NXD, 1.f, 1, 0, 0, 0);
        gemm_h<<<g, 256, GT_SMEM>>>(Xh, Wh + 1 * WN, Kh, M, NHD, NXD, 1.f, 1, 0, 0, 0);
    }
    // Vth[b] = Wv @ x_b^T               [1024,2048] per batch (half out)
    {
        dim3 g(TD / 128, NHD / 128, BD);
        gemm_h<<<g, 256, GT_SMEM>>>(Wh + 2 * WN, Xh, Vth, NHD, TD, NXD, 1.f, 1,
                                    0, (size_t)TD * NXD, (size_t)NHD * TD);
    }
    // S[b] = (Qh_b @ Kh_b^T) / sqrt(T)  [2048,2048] per batch (f32 out)
    {
        dim3 g(TD / 128, TD / 128, BD);
        gemm_h<<<g, 256, GT_SMEM>>>(Qh, Kh, S, TD, TD, NHD, scale, 0,
                                    (size_t)TD * NHD, (size_t)TD * NHD,
                                    (size_t)TD * TD);
    }
    softmax_rows<<<BD * TD, 256>>>(S, Ph);

    // Ah[b] = Ph_b @ Vth_b^T            [2048,1024] per batch (half out)
    {
        dim3 g(NHD / 128, TD / 128, BD);
        gemm_h<<<g, 256, GT_SMEM>>>(Ph, Vth, Ah, TD, NHD, TD, 1.f, 1,
                                    (size_t)TD * TD, (size_t)NHD * TD,
                                    (size_t)TD * NHD);
    }
    // out = Ah @ Wo^T                   [16384,1024] (f32 out)
    {
        dim3 g(NHD / 128, M / 128, 1);
        gemm_h<<<g, 256, GT_SMEM>>>(Ah, Wh + 3 * WN, out, M, NHD, NHD, 1.f, 0, 0, 0, 0);
    }
}

// round 7
// speedup vs baseline: 5.8015x; 1.0447x over previous
#include <cuda_runtime.h>
#include <cuda_fp16.h>
#include <math.h>
#include <stdint.h>

#define NXD 1024
#define NHD 1024
#define BD  8
#define TD  2048

// ---------------- scratch (device globals; allocation-free rule) ------------
__device__ __half g_Xh[BD * TD * NXD];             // 32 MiB
__device__ __half g_Wh[4u * NHD * NXD];            // 8 MiB
__device__ __half g_Qh[BD * TD * NHD];             // 32 MiB
__device__ __half g_Kh[BD * TD * NHD];             // 32 MiB
__device__ __half g_Vth[BD * TD * NHD];            // 32 MiB (V transposed)
__device__ float  g_S [(size_t)BD * TD * TD];      // 128 MiB (f32 scores)
__device__ __half g_Ph[(size_t)BD * TD * TD];      // 64 MiB (half probs)
__device__ __half g_Ah[BD * TD * NHD];             // 32 MiB

// ---------------- helpers ----------------------------------------------
__device__ __forceinline__ uint32_t smem_u32(const void* p) {
    uint32_t a;
    asm("{ .reg .u64 t; cvta.to.shared.u64 t, %1; cvt.u32.u64 %0, t; }"
        : "=r"(a) : "l"(p));
    return a;
}
__device__ __forceinline__ void cp_async16(uint32_t dst, const void* src) {
    asm volatile("cp.async.cg.shared.global [%0], [%1], 16;"
                 :: "r"(dst), "l"(src) : "memory");
}
__device__ __forceinline__ void mma_f16(float c[4], const uint32_t a[4], const uint32_t b[2]) {
    asm volatile(
        "mma.sync.aligned.m16n8k16.row.col.f32.f16.f16.f32 "
        "{%0,%1,%2,%3}, {%4,%5,%6,%7}, {%8,%9}, {%0,%1,%2,%3};"
        : "+f"(c[0]), "+f"(c[1]), "+f"(c[2]), "+f"(c[3])
        : "r"(a[0]), "r"(a[1]), "r"(a[2]), "r"(a[3]),
          "r"(b[0]), "r"(b[1]));
}

// ---------------------------------------------------------------------------
// fp16 mma.sync GEMM NT: C[M,N] = alpha * A[M,K] * B[N,K]^T  (A,B half)
// CTA 128(M) x 256(N), BK=64 halves, 256 threads (8 warps 2x4),
// warp tile 64x64 (32 MMAs / k16-step). 4-stage cp.async pipeline.
// out_half: 1 -> __half C, 0 -> float C.
// Requires M%128==0, N%256==0, K%64==0.
// ---------------------------------------------------------------------------
#define LROWH 72                               // 64 + 8 pad halves; 144 B/row
#define STG_HALVES ((128 + 256) * LROWH)       // A rows + B rows per stage
#define N_STAGES 4
#define GT_SMEM (N_STAGES * STG_HALVES * 2)    // 221184 B

__global__ __launch_bounds__(256, 1)
void gemm_h(const __half* __restrict__ Ag, const __half* __restrict__ Bg,
            void* __restrict__ Cg, int M, int N, int K, float alpha,
            int out_half, size_t sA, size_t sB, size_t sC)
{
    extern __shared__ __half sm[];
    const uint32_t sbase = smem_u32(sm);

    const int tid  = threadIdx.x;
    const int wid  = tid >> 5;
    const int lane = tid & 31;
    const int wm   = wid >> 2;        // 0..1  (64-row slab of 128)
    const int wn   = wid & 3;         // 0..3  (64-col slab of 256)
    const int g    = lane >> 2;       // 0..7
    const int tig  = lane & 3;        // 0..3

    const __half* Ab = Ag + blockIdx.z * sA + (size_t)blockIdx.y * 128 * K;
    const __half* Bb = Bg + blockIdx.z * sB + (size_t)blockIdx.x * 256 * K;

    float acc[4][8][4];
#pragma unroll
    for (int i = 0; i < 4; i++)
#pragma unroll
        for (int j = 0; j < 8; j++)
#pragma unroll
            for (int r = 0; r < 4; r++) acc[i][j][r] = 0.f;

    const int nk = K >> 6;            // 64-half K steps

    auto load_stage = [&](int js) {
        uint32_t stH = (uint32_t)((js % N_STAGES) * STG_HALVES);
        const __half* ga = Ab + js * 64;
        const __half* gb = Bb + js * 64;
#pragma unroll
        for (int i = 0; i < 12; i++) {
            int c   = tid + i * 256;          // 0..3071 chunks of 16B
            int row = c >> 3;                 // 0..383
            int fh  = (c & 7) << 3;           // half col 0..56
            uint32_t d = sbase + 2u * (stH + row * LROWH + fh);
            if (i < 4)  cp_async16(d, ga + (size_t)row * K + fh);
            else        cp_async16(d, gb + (size_t)(row - 128) * K + fh);
        }
        asm volatile("cp.async.commit_group;" ::: "memory");
    };

    load_stage(0);
    if (nk > 1) load_stage(1);
    if (nk > 2) load_stage(2);

    for (int ks = 0; ks < nk; ks++) {
        asm volatile("cp.async.wait_group 2;" ::: "memory");
        __syncthreads();

        const __half* sa = sm + (ks % N_STAGES) * STG_HALVES;
        const __half* sb = sa + 128 * LROWH;

        if (ks + 3 < nk) load_stage(ks + 3);   // stage (ks-1)%4: safe after sync

#pragma unroll
        for (int k16 = 0; k16 < 4; k16++) {
            const int kk = k16 * 16;
            uint32_t af[4][4], bf[8][2];
#pragma unroll
            for (int i = 0; i < 4; i++) {
                int m0 = wm * 64 + i * 16;
                af[i][0] = *(const uint32_t*)&sa[(m0 + g)     * LROWH + kk + 2 * tig];
                af[i][1] = *(const uint32_t*)&sa[(m0 + 8 + g) * LROWH + kk + 2 * tig];
                af[i][2] = *(const uint32_t*)&sa[(m0 + g)     * LROWH + kk + 2 * tig + 8];
                af[i][3] = *(const uint32_t*)&sa[(m0 + 8 + g) * LROWH + kk + 2 * tig + 8];
            }
#pragma unroll
            for (int j = 0; j < 8; j++) {
                int n0 = wn * 64 + j * 8;
                bf[j][0] = *(const uint32_t*)&sb[(n0 + g) * LROWH + kk + 2 * tig];
                bf[j][1] = *(const uint32_t*)&sb[(n0 + g) * LROWH + kk + 2 * tig + 8];
            }
#pragma unroll
            for (int i = 0; i < 4; i++)
#pragma unroll
                for (int j = 0; j < 8; j++)
                    mma_f16(acc[i][j], af[i], bf[j]);
        }
    }

    // Epilogue
#pragma unroll
    for (int i = 0; i < 4; i++) {
        size_t row0 = (size_t)blockIdx.y * 128 + wm * 64 + i * 16 + g;
        size_t col  = (size_t)blockIdx.x * 256 + wn * 64 + tig * 2;
        if (out_half) {
            __half* C0 = (__half*)Cg + blockIdx.z * sC + row0 * N + col;
            __half* C1 = C0 + 8 * (size_t)N;
#pragma unroll
            for (int j = 0; j < 8; j++) {
                *(__half2*)(C0 + j * 8) = __float22half2_rn(
                    make_float2(acc[i][j][0] * alpha, acc[i][j][1] * alpha));
                *(__half2*)(C1 + j * 8) = __float22half2_rn(
                    make_float2(acc[i][j][2] * alpha, acc[i][j][3] * alpha));
            }
        } else {
            float* C0 = (float*)Cg + blockIdx.z * sC + row0 * N + col;
            float* C1 = C0 + 8 * (size_t)N;
#pragma unroll
            for (int j = 0; j < 8; j++) {
                *(float2*)(C0 + j * 8) =
                    make_float2(acc[i][j][0] * alpha, acc[i][j][1] * alpha);
                *(float2*)(C1 + j * 8) =
                    make_float2(acc[i][j][2] * alpha, acc[i][j][3] * alpha);
            }
        }
    }
}

// ---------------------------------------------------------------------------
// f32 -> f16 conversions (RN)
// ---------------------------------------------------------------------------
__global__ __launch_bounds__(256) void cvt_h_kernel(
    const float* __restrict__ in, __half* __restrict__ out, int n4)
{
    int i = blockIdx.x * blockDim.x + threadIdx.x;
    if (i < n4) {
        float4 v = ((const float4*)in)[i];
        __half2 lo = __float22half2_rn(make_float2(v.x, v.y));
        __half2 hi = __float22half2_rn(make_float2(v.z, v.w));
        *(uint2*)(out + 4 * (size_t)i) =
            make_uint2(*(uint32_t*)&lo, *(uint32_t*)&hi);
    }
}

// 4 weight matrices in one launch (each n4 float4 elements)
__global__ __launch_bounds__(256) void cvt4_h_kernel(
    const float* __restrict__ w0, const float* __restrict__ w1,
    const float* __restrict__ w2, const float* __restrict__ w3,
    __half* __restrict__ out, int n4)
{
    int i = blockIdx.x * blockDim.x + threadIdx.x;
    if (i < 4 * n4) {
        int sel = i / n4, off = i - sel * n4;
        const float* src = (sel == 0) ? w0 : (sel == 1) ? w1 : (sel == 2) ? w2 : w3;
        float4 v = ((const float4*)src)[off];
        __half2 lo = __float22half2_rn(make_float2(v.x, v.y));
        __half2 hi = __float22half2_rn(make_float2(v.z, v.w));
        *(uint2*)(out + 4 * (size_t)i) =
            make_uint2(*(uint32_t*)&lo, *(uint32_t*)&hi);
    }
}

// ---------------------------------------------------------------------------
// Row softmax over T=2048 on f32 scores; writes half probabilities.
// ---------------------------------------------------------------------------
__global__ __launch_bounds__(256) void softmax_rows(
    const float* __restrict__ S, __half* __restrict__ P)
{
    const float* row = S + (size_t)blockIdx.x * TD;
    __half* prow = P + (size_t)blockIdx.x * TD;
    __shared__ float red[256];
    const int tid = threadIdx.x;

    float4 v0 = *(const float4*)(row + tid * 8);
    float4 v1 = *(const float4*)(row + tid * 8 + 4);
    float v[8] = {v0.x, v0.y, v0.z, v0.w, v1.x, v1.y, v1.z, v1.w};

    float m = -INFINITY;
#pragma unroll
    for (int i = 0; i < 8; i++) m = fmaxf(m, v[i]);
    red[tid] = m;
    __syncthreads();
    for (int s = 128; s > 0; s >>= 1) {
        if (tid < s) red[tid] = fmaxf(red[tid], red[tid + s]);
        __syncthreads();
    }
    m = red[0];
    __syncthreads();

    float sum = 0.f;
#pragma unroll
    for (int i = 0; i < 8; i++) {
        v[i] = __expf(v[i] - m);
        sum += v[i];
    }
    red[tid] = sum;
    __syncthreads();
    for (int s = 128; s > 0; s >>= 1) {
        if (tid < s) red[tid] += red[tid + s];
        __syncthreads();
    }
    float inv = 1.f / red[0];
    __half2 h[4];
#pragma unroll
    for (int i = 0; i < 4; i++)
        h[i] = __float22half2_rn(make_float2(v[2 * i] * inv, v[2 * i + 1] * inv));
    *(uint2*)(prow + tid * 8) =
        make_uint2(*(uint32_t*)&h[0], *(uint32_t*)&h[1]);
    *(uint2*)(prow + tid * 8 + 4) =
        make_uint2(*(uint32_t*)&h[2], *(uint32_t*)&h[3]);
}

// ---------------------------------------------------------------------------
extern "C" void kernel_launch(void* const* d_in, const int* in_sizes, int n_in,
                              void* d_out, int out_size)
{
    const float* x   = (const float*)d_in[0];
    const float* W_q = (const float*)d_in[1];
    const float* W_k = (const float*)d_in[2];
    const float* W_v = (const float*)d_in[3];
    const float* W_o = (const float*)d_in[4];
    float* out = (float*)d_out;

    __half* Xh;  cudaGetSymbolAddress((void**)&Xh,  g_Xh);
    __half* Wh;  cudaGetSymbolAddress((void**)&Wh,  g_Wh);
    __half* Qh;  cudaGetSymbolAddress((void**)&Qh,  g_Qh);
    __half* Kh;  cudaGetSymbolAddress((void**)&Kh,  g_Kh);
    __half* Vth; cudaGetSymbolAddress((void**)&Vth, g_Vth);
    float*  S;   cudaGetSymbolAddress((void**)&S,   g_S);
    __half* Ph;  cudaGetSymbolAddress((void**)&Ph,  g_Ph);
    __half* Ah;  cudaGetSymbolAddress((void**)&Ah,  g_Ah);

    cudaFuncSetAttribute(gemm_h, cudaFuncAttributeMaxDynamicSharedMemorySize, GT_SMEM);

    const int M = BD * TD;                        // 16384
    const float scale = 1.0f / sqrtf((float)TD);
    const size_t WN = (size_t)NHD * NXD;

    // Convert operands to fp16 (RN)
    cvt_h_kernel<<<(M * NXD / 4 + 255) / 256, 256>>>(x, Xh, M * NXD / 4);
    cvt4_h_kernel<<<(int)(4 * (WN / 4) + 255) / 256, 256>>>(
        W_q, W_k, W_v, W_o, Wh, (int)(WN / 4));

    // Qh = Xh @ Wq^T ; Kh = Xh @ Wk^T   [16384,1024] (half out)
    {
        dim3 g(NHD / 256, M / 128, 1);
        gemm_h<<<g, 256, GT_SMEM>>>(Xh, Wh + 0 * WN, Qh, M, NHD, NXD, 1.f, 1, 0, 0, 0);
        gemm_h<<<g, 256, GT_SMEM>>>(Xh, Wh + 1 * WN, Kh, M, NHD, NXD, 1.f, 1, 0, 0, 0);
    }
    // Vth[b] = Wv @ x_b^T               [1024,2048] per batch (half out)
    {
        dim3 g(TD / 256, NHD / 128, BD);
        gemm_h<<<g, 256, GT_SMEM>>>(Wh + 2 * WN, Xh, Vth, NHD, TD, NXD, 1.f, 1,
                                    0, (size_t)TD * NXD, (size_t)NHD * TD);
    }
    // S[b] = (Qh_b @ Kh_b^T) / sqrt(T)  [2048,2048] per batch (f32 out)
    {
        dim3 g(TD / 256, TD / 128, BD);
        gemm_h<<<g, 256, GT_SMEM>>>(Qh, Kh, S, TD, TD, NHD, scale, 0,
                                    (size_t)TD * NHD, (size_t)TD * NHD,
                                    (size_t)TD * TD);
    }
    softmax_rows<<<BD * TD, 256>>>(S, Ph);

    // Ah[b] = Ph_b @ Vth_b^T            [2048,1024] per batch (half out)
    {
        dim3 g(NHD / 256, TD / 128, BD);
        gemm_h<<<g, 256, GT_SMEM>>>(Ph, Vth, Ah, TD, NHD, TD, 1.f, 1,
                                    (size_t)TD * TD, (size_t)NHD * TD,
                                    (size_t)TD * NHD);
    }
    // out = Ah @ Wo^T                   [16384,1024] (f32 out)
    {
        dim3 g(NHD / 256, M / 128, 1);
        gemm_h<<<g, 256, GT_SMEM>>>(Ah, Wh + 3 * WN, out, M, NHD, NHD, 1.f, 0, 0, 0, 0);
    }
}

// round 8
// speedup vs baseline: 6.0323x; 1.0398x over previous
#include <cuda_runtime.h>
#include <cuda_fp16.h>
#include <math.h>
#include <stdint.h>

#define NXD 1024
#define NHD 1024
#define BD  8
#define TD  2048

// ---------------- scratch (device globals; allocation-free rule) ------------
__device__ __half g_Xh[BD * TD * NXD];             // 32 MiB
__device__ __half g_Wh[4u * NHD * NXD];            // 8 MiB
__device__ __half g_Qh[BD * TD * NHD];             // 32 MiB
__device__ __half g_Kh[BD * TD * NHD];             // 32 MiB
__device__ __half g_Vth[BD * TD * NHD];            // 32 MiB (V transposed)
__device__ float  g_S [(size_t)BD * TD * TD];      // 128 MiB (f32 scores)
__device__ __half g_Ph[(size_t)BD * TD * TD];      // 64 MiB (half probs)
__device__ __half g_Ah[BD * TD * NHD];             // 32 MiB

// ---------------- helpers ----------------------------------------------
__device__ __forceinline__ uint32_t smem_u32(const void* p) {
    uint32_t a;
    asm("{ .reg .u64 t; cvta.to.shared.u64 t, %1; cvt.u32.u64 %0, t; }"
        : "=r"(a) : "l"(p));
    return a;
}
__device__ __forceinline__ void cp_async16(uint32_t dst, const void* src) {
    asm volatile("cp.async.cg.shared.global [%0], [%1], 16;"
                 :: "r"(dst), "l"(src) : "memory");
}
__device__ __forceinline__ void mma_f16(float c[4], const uint32_t a[4], const uint32_t b[2]) {
    asm volatile(
        "mma.sync.aligned.m16n8k16.row.col.f32.f16.f16.f32 "
        "{%0,%1,%2,%3}, {%4,%5,%6,%7}, {%8,%9}, {%0,%1,%2,%3};"
        : "+f"(c[0]), "+f"(c[1]), "+f"(c[2]), "+f"(c[3])
        : "r"(a[0]), "r"(a[1]), "r"(a[2]), "r"(a[3]),
          "r"(b[0]), "r"(b[1]));
}
__device__ __forceinline__ void ldsm_x4(uint32_t r[4], uint32_t addr) {
    asm volatile("ldmatrix.sync.aligned.m8n8.x4.shared.b16 {%0,%1,%2,%3}, [%4];"
                 : "=r"(r[0]), "=r"(r[1]), "=r"(r[2]), "=r"(r[3]) : "r"(addr));
}

// ---------------------------------------------------------------------------
// fp16 mma.sync GEMM NT: C[M,N] = alpha * A[M,K] * B[N,K]^T  (A,B half)
// CTA 128(M) x 256(N), BK=64 halves, 256 threads (8 warps 2x4),
// warp tile 64x64. Fragments via ldmatrix.x4 (8 LDSM / k16-step).
// 4-stage cp.async pipeline. out_half: 1 -> __half C, 0 -> float C.
// Requires M%128==0, N%256==0, K%64==0.
// ---------------------------------------------------------------------------
#define LROWH 72                               // 64 + 8 pad halves; 144 B/row
#define STG_HALVES ((128 + 256) * LROWH)       // A rows + B rows per stage
#define N_STAGES 4
#define GT_SMEM (N_STAGES * STG_HALVES * 2)    // 221184 B

__global__ __launch_bounds__(256, 1)
void gemm_h(const __half* __restrict__ Ag, const __half* __restrict__ Bg,
            void* __restrict__ Cg, int M, int N, int K, float alpha,
            int out_half, size_t sA, size_t sB, size_t sC)
{
    extern __shared__ __half sm[];
    const uint32_t sbase = smem_u32(sm);

    const int tid  = threadIdx.x;
    const int wid  = tid >> 5;
    const int lane = tid & 31;
    const int wm   = wid >> 2;        // 0..1  (64-row slab of 128)
    const int wn   = wid & 3;         // 0..3  (64-col slab of 256)
    const int g    = lane >> 2;       // 0..7
    const int tig  = lane & 3;        // 0..3

    // ldmatrix lane->address geometry
    const int l7 = lane & 7;          // row within 8x8 tile
    const int t4 = lane >> 3;         // tile index 0..3

    const __half* Ab = Ag + blockIdx.z * sA + (size_t)blockIdx.y * 128 * K;
    const __half* Bb = Bg + blockIdx.z * sB + (size_t)blockIdx.x * 256 * K;

    float acc[4][8][4];
#pragma unroll
    for (int i = 0; i < 4; i++)
#pragma unroll
        for (int j = 0; j < 8; j++)
#pragma unroll
            for (int r = 0; r < 4; r++) acc[i][j][r] = 0.f;

    const int nk = K >> 6;            // 64-half K steps

    auto load_stage = [&](int js) {
        uint32_t stH = (uint32_t)((js % N_STAGES) * STG_HALVES);
        const __half* ga = Ab + js * 64;
        const __half* gb = Bb + js * 64;
#pragma unroll
        for (int i = 0; i < 12; i++) {
            int c   = tid + i * 256;          // 0..3071 chunks of 16B
            int row = c >> 3;                 // 0..383
            int fh  = (c & 7) << 3;           // half col 0..56
            uint32_t d = sbase + 2u * (stH + row * LROWH + fh);
            if (i < 4)  cp_async16(d, ga + (size_t)row * K + fh);
            else        cp_async16(d, gb + (size_t)(row - 128) * K + fh);
        }
        asm volatile("cp.async.commit_group;" ::: "memory");
    };

    load_stage(0);
    if (nk > 1) load_stage(1);
    if (nk > 2) load_stage(2);

    // Per-lane ldmatrix offsets (halves), constant across the k-loop.
    // A tiles for m16 block i: t0=(row, kk) t1=(row+8, kk) t2=(row, kk+8) t3=(row+8, kk+8)
    const uint32_t aoff = (uint32_t)((wm * 64 + ((t4 & 1) << 3) + l7) * LROWH
                                     + ((t4 >> 1) << 3));
    // B tiles for n16 pair jj: t0=(n, kk) t1=(n, kk+8) t2=(n+8, kk) t3=(n+8, kk+8)
    uint32_t boff[4];
#pragma unroll
    for (int jj = 0; jj < 4; jj++)
        boff[jj] = (uint32_t)((wn * 64 + jj * 16 + ((t4 >> 1) << 3) + l7) * LROWH
                              + ((t4 & 1) << 3));

    for (int ks = 0; ks < nk; ks++) {
        asm volatile("cp.async.wait_group 2;" ::: "memory");
        __syncthreads();

        const uint32_t saA = sbase + 2u * (uint32_t)((ks % N_STAGES) * STG_HALVES);
        const uint32_t saB = saA + 2u * 128 * LROWH;

        if (ks + 3 < nk) load_stage(ks + 3);   // stage (ks-1)%4: safe after sync

#pragma unroll
        for (int k16 = 0; k16 < 4; k16++) {
            const uint32_t kk = k16 * 16;
            uint32_t af[4][4], bf[4][4];
#pragma unroll
            for (int i = 0; i < 4; i++)
                ldsm_x4(af[i], saA + 2u * (aoff + i * 16 * LROWH + kk));
#pragma unroll
            for (int jj = 0; jj < 4; jj++)
                ldsm_x4(bf[jj], saB + 2u * (boff[jj] + kk));
#pragma unroll
            for (int i = 0; i < 4; i++)
#pragma unroll
                for (int j = 0; j < 8; j++)
                    mma_f16(acc[i][j], af[i], &bf[j >> 1][(j & 1) * 2]);
        }
    }

    // Epilogue
#pragma unroll
    for (int i = 0; i < 4; i++) {
        size_t row0 = (size_t)blockIdx.y * 128 + wm * 64 + i * 16 + g;
        size_t col  = (size_t)blockIdx.x * 256 + wn * 64 + tig * 2;
        if (out_half) {
            __half* C0 = (__half*)Cg + blockIdx.z * sC + row0 * N + col;
            __half* C1 = C0 + 8 * (size_t)N;
#pragma unroll
            for (int j = 0; j < 8; j++) {
                *(__half2*)(C0 + j * 8) = __float22half2_rn(
                    make_float2(acc[i][j][0] * alpha, acc[i][j][1] * alpha));
                *(__half2*)(C1 + j * 8) = __float22half2_rn(
                    make_float2(acc[i][j][2] * alpha, acc[i][j][3] * alpha));
            }
        } else {
            float* C0 = (float*)Cg + blockIdx.z * sC + row0 * N + col;
            float* C1 = C0 + 8 * (size_t)N;
#pragma unroll
            for (int j = 0; j < 8; j++) {
                *(float2*)(C0 + j * 8) =
                    make_float2(acc[i][j][0] * alpha, acc[i][j][1] * alpha);
                *(float2*)(C1 + j * 8) =
                    make_float2(acc[i][j][2] * alpha, acc[i][j][3] * alpha);
            }
        }
    }
}

// ---------------------------------------------------------------------------
// f32 -> f16 conversions (RN)
// ---------------------------------------------------------------------------
__global__ __launch_bounds__(256) void cvt_h_kernel(
    const float* __restrict__ in, __half* __restrict__ out, int n4)
{
    int i = blockIdx.x * blockDim.x + threadIdx.x;
    if (i < n4) {
        float4 v = ((const float4*)in)[i];
        __half2 lo = __float22half2_rn(make_float2(v.x, v.y));
        __half2 hi = __float22half2_rn(make_float2(v.z, v.w));
        *(uint2*)(out + 4 * (size_t)i) =
            make_uint2(*(uint32_t*)&lo, *(uint32_t*)&hi);
    }
}

// 4 weight matrices in one launch (each n4 float4 elements)
__global__ __launch_bounds__(256) void cvt4_h_kernel(
    const float* __restrict__ w0, const float* __restrict__ w1,
    const float* __restrict__ w2, const float* __restrict__ w3,
    __half* __restrict__ out, int n4)
{
    int i = blockIdx.x * blockDim.x + threadIdx.x;
    if (i < 4 * n4) {
        int sel = i / n4, off = i - sel * n4;
        const float* src = (sel == 0) ? w0 : (sel == 1) ? w1 : (sel == 2) ? w2 : w3;
        float4 v = ((const float4*)src)[off];
        __half2 lo = __float22half2_rn(make_float2(v.x, v.y));
        __half2 hi = __float22half2_rn(make_float2(v.z, v.w));
        *(uint2*)(out + 4 * (size_t)i) =
            make_uint2(*(uint32_t*)&lo, *(uint32_t*)&hi);
    }
}

// ---------------------------------------------------------------------------
// Row softmax over T=2048 on f32 scores; writes half probabilities.
// ---------------------------------------------------------------------------
__global__ __launch_bounds__(256) void softmax_rows(
    const float* __restrict__ S, __half* __restrict__ P)
{
    const float* row = S + (size_t)blockIdx.x * TD;
    __half* prow = P + (size_t)blockIdx.x * TD;
    __shared__ float red[256];
    const int tid = threadIdx.x;

    float4 v0 = *(const float4*)(row + tid * 8);
    float4 v1 = *(const float4*)(row + tid * 8 + 4);
    float v[8] = {v0.x, v0.y, v0.z, v0.w, v1.x, v1.y, v1.z, v1.w};

    float m = -INFINITY;
#pragma unroll
    for (int i = 0; i < 8; i++) m = fmaxf(m, v[i]);
    red[tid] = m;
    __syncthreads();
    for (int s = 128; s > 0; s >>= 1) {
        if (tid < s) red[tid] = fmaxf(red[tid], red[tid + s]);
        __syncthreads();
    }
    m = red[0];
    __syncthreads();

    float sum = 0.f;
#pragma unroll
    for (int i = 0; i < 8; i++) {
        v[i] = __expf(v[i] - m);
        sum += v[i];
    }
    red[tid] = sum;
    __syncthreads();
    for (int s = 128; s > 0; s >>= 1) {
        if (tid < s) red[tid] += red[tid + s];
        __syncthreads();
    }
    float inv = 1.f / red[0];
    __half2 h[4];
#pragma unroll
    for (int i = 0; i < 4; i++)
        h[i] = __float22half2_rn(make_float2(v[2 * i] * inv, v[2 * i + 1] * inv));
    *(uint2*)(prow + tid * 8) =
        make_uint2(*(uint32_t*)&h[0], *(uint32_t*)&h[1]);
    *(uint2*)(prow + tid * 8 + 4) =
        make_uint2(*(uint32_t*)&h[2], *(uint32_t*)&h[3]);
}

// ---------------------------------------------------------------------------
extern "C" void kernel_launch(void* const* d_in, const int* in_sizes, int n_in,
                              void* d_out, int out_size)
{
    const float* x   = (const float*)d_in[0];
    const float* W_q = (const float*)d_in[1];
    const float* W_k = (const float*)d_in[2];
    const float* W_v = (const float*)d_in[3];
    const float* W_o = (const float*)d_in[4];
    float* out = (float*)d_out;

    __half* Xh;  cudaGetSymbolAddress((void**)&Xh,  g_Xh);
    __half* Wh;  cudaGetSymbolAddress((void**)&Wh,  g_Wh);
    __half* Qh;  cudaGetSymbolAddress((void**)&Qh,  g_Qh);
    __half* Kh;  cudaGetSymbolAddress((void**)&Kh,  g_Kh);
    __half* Vth; cudaGetSymbolAddress((void**)&Vth, g_Vth);
    float*  S;   cudaGetSymbolAddress((void**)&S,   g_S);
    __half* Ph;  cudaGetSymbolAddress((void**)&Ph,  g_Ph);
    __half* Ah;  cudaGetSymbolAddress((void**)&Ah,  g_Ah);

    cudaFuncSetAttribute(gemm_h, cudaFuncAttributeMaxDynamicSharedMemorySize, GT_SMEM);

    const int M = BD * TD;                        // 16384
    const float scale = 1.0f / sqrtf((float)TD);
    const size_t WN = (size_t)NHD * NXD;

    // Convert operands to fp16 (RN)
    cvt_h_kernel<<<(M * NXD / 4 + 255) / 256, 256>>>(x, Xh, M * NXD / 4);
    cvt4_h_kernel<<<(int)(4 * (WN / 4) + 255) / 256, 256>>>(
        W_q, W_k, W_v, W_o, Wh, (int)(WN / 4));

    // Qh = Xh @ Wq^T ; Kh = Xh @ Wk^T   [16384,1024] (half out)
    {
        dim3 g(NHD / 256, M / 128, 1);
        gemm_h<<<g, 256, GT_SMEM>>>(Xh, Wh + 0 * WN, Qh, M, NHD, NXD, 1.f, 1, 0, 0, 0);
        gemm_h<<<g, 256, GT_SMEM>>>(Xh, Wh + 1 * WN, Kh, M, NHD, NXD, 1.f, 1, 0, 0, 0);
    }
    // Vth[b] = Wv @ x_b^T               [1024,2048] per batch (half out)
    {
        dim3 g(TD / 256, NHD / 128, BD);
        gemm_h<<<g, 256, GT_SMEM>>>(Wh + 2 * WN, Xh, Vth, NHD, TD, NXD, 1.f, 1,
                                    0, (size_t)TD * NXD, (size_t)NHD * TD);
    }
    // S[b] = (Qh_b @ Kh_b^T) / sqrt(T)  [2048,2048] per batch (f32 out)
    {
        dim3 g(TD / 256, TD / 128, BD);
        gemm_h<<<g, 256, GT_SMEM>>>(Qh, Kh, S, TD, TD, NHD, scale, 0,
                                    (size_t)TD * NHD, (size_t)TD * NHD,
                                    (size_t)TD * TD);
    }
    softmax_rows<<<BD * TD, 256>>>(S, Ph);

    // Ah[b] = Ph_b @ Vth_b^T            [2048,1024] per batch (half out)
    {
        dim3 g(NHD / 256, TD / 128, BD);
        gemm_h<<<g, 256, GT_SMEM>>>(Ph, Vth, Ah, TD, NHD, TD, 1.f, 1,
                                    (size_t)TD * TD, (size_t)NHD * TD,
                                    (size_t)TD * NHD);
    }
    // out = Ah @ Wo^T                   [16384,1024] (f32 out)
    {
        dim3 g(NHD / 256, M / 128, 1);
        gemm_h<<<g, 256, GT_SMEM>>>(Ah, Wh + 3 * WN, out, M, NHD, NHD, 1.f, 0, 0, 0, 0);
    }
}

// round 9
// speedup vs baseline: 6.8645x; 1.1380x over previous
#include <cuda_runtime.h>
#include <cuda_fp16.h>
#include <math.h>
#include <stdint.h>

#define NXD 1024
#define NHD 1024
#define BD  8
#define TD  2048

// ---------------- scratch (device globals; allocation-free rule) ------------
__device__ __half g_Xh[BD * TD * NXD];             // 32 MiB
__device__ __half g_Wh[4u * NHD * NXD];            // 8 MiB
__device__ __half g_Qh[BD * TD * NHD];             // 32 MiB
__device__ __half g_Kh[BD * TD * NHD];             // 32 MiB
__device__ __half g_Vth[BD * TD * NHD];            // 32 MiB (V transposed)
__device__ float  g_S [(size_t)BD * TD * TD];      // 128 MiB (f32 scores)
__device__ __half g_Ph[(size_t)BD * TD * TD];      // 64 MiB (half probs)
__device__ __half g_Ah[BD * TD * NHD];             // 32 MiB

// ---------------- helpers ----------------------------------------------
__device__ __forceinline__ uint32_t smem_u32(const void* p) {
    uint32_t a;
    asm("{ .reg .u64 t; cvta.to.shared.u64 t, %1; cvt.u32.u64 %0, t; }"
        : "=r"(a) : "l"(p));
    return a;
}
__device__ __forceinline__ void cp_async16(uint32_t dst, const void* src) {
    asm volatile("cp.async.cg.shared.global [%0], [%1], 16;"
                 :: "r"(dst), "l"(src) : "memory");
}
__device__ __forceinline__ void mma_f16(float c[4], const uint32_t a[4], const uint32_t b[2]) {
    asm volatile(
        "mma.sync.aligned.m16n8k16.row.col.f32.f16.f16.f32 "
        "{%0,%1,%2,%3}, {%4,%5,%6,%7}, {%8,%9}, {%0,%1,%2,%3};"
        : "+f"(c[0]), "+f"(c[1]), "+f"(c[2]), "+f"(c[3])
        : "r"(a[0]), "r"(a[1]), "r"(a[2]), "r"(a[3]),
          "r"(b[0]), "r"(b[1]));
}
__device__ __forceinline__ void ldsm_x4(uint32_t r[4], uint32_t addr) {
    asm volatile("ldmatrix.sync.aligned.m8n8.x4.shared.b16 {%0,%1,%2,%3}, [%4];"
                 : "=r"(r[0]), "=r"(r[1]), "=r"(r[2]), "=r"(r[3]) : "r"(addr));
}

// ---------------------------------------------------------------------------
// fp16 mma.sync GEMM NT: C[M,N] = alpha * A[M,K] * B[N,K]^T  (A,B half)
// CTA 128(M) x 128(N), BK=64 halves, 256 threads (8 warps 2x4),
// warp tile 64x32. Fragments via ldmatrix.x4 (6 LDSM / k16-step).
// 3-stage cp.async pipeline; 2 CTAs/SM (4 warps/SMSP) for latency hiding.
// out_half: 1 -> __half C, 0 -> float C.
// Requires M%128==0, N%128==0, K%64==0.
// ---------------------------------------------------------------------------
#define LROWH 72                               // 64 + 8 pad halves; 144 B/row
#define STG_HALVES ((128 + 128) * LROWH)       // A rows + B rows per stage
#define N_STAGES 3
#define GT_SMEM (N_STAGES * STG_HALVES * 2)    // 110592 B -> 2 CTAs/SM

__global__ __launch_bounds__(256, 2)
void gemm_h(const __half* __restrict__ Ag, const __half* __restrict__ Bg,
            void* __restrict__ Cg, int M, int N, int K, float alpha,
            int out_half, size_t sA, size_t sB, size_t sC)
{
    extern __shared__ __half sm[];
    const uint32_t sbase = smem_u32(sm);

    const int tid  = threadIdx.x;
    const int wid  = tid >> 5;
    const int lane = tid & 31;
    const int wm   = wid >> 2;        // 0..1  (64-row slab of 128)
    const int wn   = wid & 3;         // 0..3  (32-col slab of 128)
    const int g    = lane >> 2;       // 0..7
    const int tig  = lane & 3;        // 0..3

    // ldmatrix lane->address geometry
    const int l7 = lane & 7;          // row within 8x8 tile
    const int t4 = lane >> 3;         // tile index 0..3

    const __half* Ab = Ag + blockIdx.z * sA + (size_t)blockIdx.y * 128 * K;
    const __half* Bb = Bg + blockIdx.z * sB + (size_t)blockIdx.x * 128 * K;

    float acc[4][4][4];
#pragma unroll
    for (int i = 0; i < 4; i++)
#pragma unroll
        for (int j = 0; j < 4; j++)
#pragma unroll
            for (int r = 0; r < 4; r++) acc[i][j][r] = 0.f;

    const int nk = K >> 6;            // 64-half K steps

    auto load_stage = [&](int js) {
        uint32_t stH = (uint32_t)((js % N_STAGES) * STG_HALVES);
        const __half* ga = Ab + js * 64;
        const __half* gb = Bb + js * 64;
#pragma unroll
        for (int i = 0; i < 8; i++) {
            int c   = tid + i * 256;          // 0..2047 chunks of 16B
            int row = c >> 3;                 // 0..255
            int fh  = (c & 7) << 3;           // half col 0..56
            uint32_t d = sbase + 2u * (stH + row * LROWH + fh);
            if (i < 4)  cp_async16(d, ga + (size_t)row * K + fh);
            else        cp_async16(d, gb + (size_t)(row - 128) * K + fh);
        }
        asm volatile("cp.async.commit_group;" ::: "memory");
    };

    load_stage(0);
    if (nk > 1) load_stage(1);

    // Per-lane ldmatrix offsets (halves), constant across the k-loop.
    // A tiles for m16 block i: t0=(row, kk) t1=(row+8, kk) t2=(row, kk+8) t3=(row+8, kk+8)
    const uint32_t aoff = (uint32_t)((wm * 64 + ((t4 & 1) << 3) + l7) * LROWH
                                     + ((t4 >> 1) << 3));
    // B tiles for n16 pair jj: t0=(n, kk) t1=(n, kk+8) t2=(n+8, kk) t3=(n+8, kk+8)
    uint32_t boff[2];
#pragma unroll
    for (int jj = 0; jj < 2; jj++)
        boff[jj] = (uint32_t)((wn * 32 + jj * 16 + ((t4 >> 1) << 3) + l7) * LROWH
                              + ((t4 & 1) << 3));

    for (int ks = 0; ks < nk; ks++) {
        asm volatile("cp.async.wait_group 1;" ::: "memory");
        __syncthreads();

        const uint32_t saA = sbase + 2u * (uint32_t)((ks % N_STAGES) * STG_HALVES);
        const uint32_t saB = saA + 2u * 128 * LROWH;

        if (ks + 2 < nk) load_stage(ks + 2);   // stage (ks-1)%3: safe after sync

#pragma unroll
        for (int k16 = 0; k16 < 4; k16++) {
            const uint32_t kk = k16 * 16;
            uint32_t af[4][4], bf[2][4];
#pragma unroll
            for (int i = 0; i < 4; i++)
                ldsm_x4(af[i], saA + 2u * (aoff + i * 16 * LROWH + kk));
#pragma unroll
            for (int jj = 0; jj < 2; jj++)
                ldsm_x4(bf[jj], saB + 2u * (boff[jj] + kk));
#pragma unroll
            for (int i = 0; i < 4; i++)
#pragma unroll
                for (int j = 0; j < 4; j++)
                    mma_f16(acc[i][j], af[i], &bf[j >> 1][(j & 1) * 2]);
        }
    }

    // Epilogue
#pragma unroll
    for (int i = 0; i < 4; i++) {
        size_t row0 = (size_t)blockIdx.y * 128 + wm * 64 + i * 16 + g;
        size_t col  = (size_t)blockIdx.x * 128 + wn * 32 + tig * 2;
        if (out_half) {
            __half* C0 = (__half*)Cg + blockIdx.z * sC + row0 * N + col;
            __half* C1 = C0 + 8 * (size_t)N;
#pragma unroll
            for (int j = 0; j < 4; j++) {
                *(__half2*)(C0 + j * 8) = __float22half2_rn(
                    make_float2(acc[i][j][0] * alpha, acc[i][j][1] * alpha));
                *(__half2*)(C1 + j * 8) = __float22half2_rn(
                    make_float2(acc[i][j][2] * alpha, acc[i][j][3] * alpha));
            }
        } else {
            float* C0 = (float*)Cg + blockIdx.z * sC + row0 * N + col;
            float* C1 = C0 + 8 * (size_t)N;
#pragma unroll
            for (int j = 0; j < 4; j++) {
                *(float2*)(C0 + j * 8) =
                    make_float2(acc[i][j][0] * alpha, acc[i][j][1] * alpha);
                *(float2*)(C1 + j * 8) =
                    make_float2(acc[i][j][2] * alpha, acc[i][j][3] * alpha);
            }
        }
    }
}

// ---------------------------------------------------------------------------
// f32 -> f16 conversions (RN)
// ---------------------------------------------------------------------------
__global__ __launch_bounds__(256) void cvt_h_kernel(
    const float* __restrict__ in, __half* __restrict__ out, int n4)
{
    int i = blockIdx.x * blockDim.x + threadIdx.x;
    if (i < n4) {
        float4 v = ((const float4*)in)[i];
        __half2 lo = __float22half2_rn(make_float2(v.x, v.y));
        __half2 hi = __float22half2_rn(make_float2(v.z, v.w));
        *(uint2*)(out + 4 * (size_t)i) =
            make_uint2(*(uint32_t*)&lo, *(uint32_t*)&hi);
    }
}

// 4 weight matrices in one launch (each n4 float4 elements)
__global__ __launch_bounds__(256) void cvt4_h_kernel(
    const float* __restrict__ w0, const float* __restrict__ w1,
    const float* __restrict__ w2, const float* __restrict__ w3,
    __half* __restrict__ out, int n4)
{
    int i = blockIdx.x * blockDim.x + threadIdx.x;
    if (i < 4 * n4) {
        int sel = i / n4, off = i - sel * n4;
        const float* src = (sel == 0) ? w0 : (sel == 1) ? w1 : (sel == 2) ? w2 : w3;
        float4 v = ((const float4*)src)[off];
        __half2 lo = __float22half2_rn(make_float2(v.x, v.y));
        __half2 hi = __float22half2_rn(make_float2(v.z, v.w));
        *(uint2*)(out + 4 * (size_t)i) =
            make_uint2(*(uint32_t*)&lo, *(uint32_t*)&hi);
    }
}

// ---------------------------------------------------------------------------
// Row softmax over T=2048 on f32 scores; writes half probabilities.
// ---------------------------------------------------------------------------
__global__ __launch_bounds__(256) void softmax_rows(
    const float* __restrict__ S, __half* __restrict__ P)
{
    const float* row = S + (size_t)blockIdx.x * TD;
    __half* prow = P + (size_t)blockIdx.x * TD;
    __shared__ float red[256];
    const int tid = threadIdx.x;

    float4 v0 = *(const float4*)(row + tid * 8);
    float4 v1 = *(const float4*)(row + tid * 8 + 4);
    float v[8] = {v0.x, v0.y, v0.z, v0.w, v1.x, v1.y, v1.z, v1.w};

    float m = -INFINITY;
#pragma unroll
    for (int i = 0; i < 8; i++) m = fmaxf(m, v[i]);
    red[tid] = m;
    __syncthreads();
    for (int s = 128; s > 0; s >>= 1) {
        if (tid < s) red[tid] = fmaxf(red[tid], red[tid + s]);
        __syncthreads();
    }
    m = red[0];
    __syncthreads();

    float sum = 0.f;
#pragma unroll
    for (int i = 0; i < 8; i++) {
        v[i] = __expf(v[i] - m);
        sum += v[i];
    }
    red[tid] = sum;
    __syncthreads();
    for (int s = 128; s > 0; s >>= 1) {
        if (tid < s) red[tid] += red[tid + s];
        __syncthreads();
    }
    float inv = 1.f / red[0];
    __half2 h[4];
#pragma unroll
    for (int i = 0; i < 4; i++)
        h[i] = __float22half2_rn(make_float2(v[2 * i] * inv, v[2 * i + 1] * inv));
    *(uint2*)(prow + tid * 8) =
        make_uint2(*(uint32_t*)&h[0], *(uint32_t*)&h[1]);
    *(uint2*)(prow + tid * 8 + 4) =
        make_uint2(*(uint32_t*)&h[2], *(uint32_t*)&h[3]);
}

// ---------------------------------------------------------------------------
extern "C" void kernel_launch(void* const* d_in, const int* in_sizes, int n_in,
                              void* d_out, int out_size)
{
    const float* x   = (const float*)d_in[0];
    const float* W_q = (const float*)d_in[1];
    const float* W_k = (const float*)d_in[2];
    const float* W_v = (const float*)d_in[3];
    const float* W_o = (const float*)d_in[4];
    float* out = (float*)d_out;

    __half* Xh;  cudaGetSymbolAddress((void**)&Xh,  g_Xh);
    __half* Wh;  cudaGetSymbolAddress((void**)&Wh,  g_Wh);
    __half* Qh;  cudaGetSymbolAddress((void**)&Qh,  g_Qh);
    __half* Kh;  cudaGetSymbolAddress((void**)&Kh,  g_Kh);
    __half* Vth; cudaGetSymbolAddress((void**)&Vth, g_Vth);
    float*  S;   cudaGetSymbolAddress((void**)&S,   g_S);
    __half* Ph;  cudaGetSymbolAddress((void**)&Ph,  g_Ph);
    __half* Ah;  cudaGetSymbolAddress((void**)&Ah,  g_Ah);

    cudaFuncSetAttribute(gemm_h, cudaFuncAttributeMaxDynamicSharedMemorySize, GT_SMEM);

    const int M = BD * TD;                        // 16384
    const float scale = 1.0f / sqrtf((float)TD);
    const size_t WN = (size_t)NHD * NXD;

    // Convert operands to fp16 (RN)
    cvt_h_kernel<<<(M * NXD / 4 + 255) / 256, 256>>>(x, Xh, M * NXD / 4);
    cvt4_h_kernel<<<(int)(4 * (WN / 4) + 255) / 256, 256>>>(
        W_q, W_k, W_v, W_o, Wh, (int)(WN / 4));

    // Qh = Xh @ Wq^T ; Kh = Xh @ Wk^T   [16384,1024] (half out)
    {
        dim3 g(NHD / 128, M / 128, 1);
        gemm_h<<<g, 256, GT_SMEM>>>(Xh, Wh + 0 * WN, Qh, M, NHD, NXD, 1.f, 1, 0, 0, 0);
        gemm_h<<<g, 256, GT_SMEM>>>(Xh, Wh + 1 * WN, Kh, M, NHD, NXD, 1.f, 1, 0, 0, 0);
    }
    // Vth[b] = Wv @ x_b^T               [1024,2048] per batch (half out)
    {
        dim3 g(TD / 128, NHD / 128, BD);
        gemm_h<<<g, 256, GT_SMEM>>>(Wh + 2 * WN, Xh, Vth, NHD, TD, NXD, 1.f, 1,
                                    0, (size_t)TD * NXD, (size_t)NHD * TD);
    }
    // S[b] = (Qh_b @ Kh_b^T) / sqrt(T)  [2048,2048] per batch (f32 out)
    {
        dim3 g(TD / 128, TD / 128, BD);
        gemm_h<<<g, 256, GT_SMEM>>>(Qh, Kh, S, TD, TD, NHD, scale, 0,
                                    (size_t)TD * NHD, (size_t)TD * NHD,
                                    (size_t)TD * TD);
    }
    softmax_rows<<<BD * TD, 256>>>(S, Ph);

    // Ah[b] = Ph_b @ Vth_b^T            [2048,1024] per batch (half out)
    {
        dim3 g(NHD / 128, TD / 128, BD);
        gemm_h<<<g, 256, GT_SMEM>>>(Ph, Vth, Ah, TD, NHD, TD, 1.f, 1,
                                    (size_t)TD * TD, (size_t)NHD * TD,
                                    (size_t)TD * NHD);
    }
    // out = Ah @ Wo^T                   [16384,1024] (f32 out)
    {
        dim3 g(NHD / 128, M / 128, 1);
        gemm_h<<<g, 256, GT_SMEM>>>(Ah, Wh + 3 * WN, out, M, NHD, NHD, 1.f, 0, 0, 0, 0);
    }
}